// round 3
// baseline (speedup 1.0000x reference)
#include <cuda_runtime.h>
#include <cuda_bf16.h>

// Segment-mean: out[s,:] = mean_{i: label[i]==s} node_input[i,:]
// N=200000, DIM=480 (dim4=120 float4), NSEG=4096.
// Pipeline (4 kernels, no global-memory init pass needed):
//   k_hist    : per-block private histograms -> g_ph (no atomics on gmem)
//   k_scan    : sum partials + warp-shuffle scan -> offsets & cursor
//   k_scatter : CSR node-id list via gmem atomics on cursor
//   k_reduce  : one CTA per segment, smem-staged index list, float4 gather-reduce

#define N_MAX   262144
#define S_MAX   4096
#define NB_HIST 128     // hist blocks (also the partial-count in scan)

__device__ __align__(16) int g_ph[NB_HIST * S_MAX];
__device__ __align__(16) int g_offsets[S_MAX + 4];
__device__ __align__(16) int g_cursor[S_MAX];
__device__ int g_order[N_MAX];

// ---- label dtype sniff: read first 32 int64 words; if any is out of
// [0,nseg) the buffer must be packed int32. P(misdetect) ~ 4096^-32.
__device__ __forceinline__ int sniff_lab32(const void* labels, int n, int nseg) {
    const long long* p = (const long long*)labels;
    int words = n >> 1; if (words > 32) words = 32;
    int bad = 0;
    for (int i = 0; i < words; i++) {
        long long v = p[i];
        if (v < 0 || v >= (long long)nseg) bad = 1;
    }
    return bad;
}

__device__ __forceinline__ int load_label(const void* p, int i, int lab32) {
    if (lab32) return ((const int*)p)[i];
    return (int)(((const long long*)p)[i]);
}

// ---------------------------------------------------------------- hist
__global__ void k_hist(const void* __restrict__ labels, int n, int nseg) {
    __shared__ int h[S_MAX];
    __shared__ int s_lab32;
    if (threadIdx.x == 0) s_lab32 = sniff_lab32(labels, n, nseg);
    for (int i = threadIdx.x; i < S_MAX; i += blockDim.x) h[i] = 0;
    __syncthreads();
    int lab32 = s_lab32;
    for (int i = blockIdx.x * blockDim.x + threadIdx.x; i < n;
         i += gridDim.x * blockDim.x) {
        atomicAdd(&h[load_label(labels, i, lab32)], 1);
    }
    __syncthreads();
    int4* dst = (int4*)(g_ph + blockIdx.x * S_MAX);
    const int4* src = (const int4*)h;
    for (int i = threadIdx.x; i < S_MAX / 4; i += blockDim.x) dst[i] = src[i];
}

// ---------------------------------------------------------------- scan (1 CTA, 1024 thr)
__global__ void k_scan(int nseg) {
    __shared__ int wsum[32];
    int t = threadIdx.x;
    int lane = t & 31, warp = t >> 5;

    int4 c = make_int4(0, 0, 0, 0);
    #pragma unroll 4
    for (int p = 0; p < NB_HIST; p++) {
        int4 v = ((const int4*)(g_ph + p * S_MAX))[t];
        c.x += v.x; c.y += v.y; c.z += v.z; c.w += v.w;
    }
    int s = c.x + c.y + c.z + c.w;

    // inclusive warp scan of thread sums
    int v = s;
    #pragma unroll
    for (int off = 1; off < 32; off <<= 1) {
        int u = __shfl_up_sync(0xffffffffu, v, off);
        if (lane >= off) v += u;
    }
    if (lane == 31) wsum[warp] = v;
    __syncthreads();
    if (warp == 0) {
        int w = wsum[lane];
        #pragma unroll
        for (int off = 1; off < 32; off <<= 1) {
            int u = __shfl_up_sync(0xffffffffu, w, off);
            if (lane >= off) w += u;
        }
        wsum[lane] = w;
    }
    __syncthreads();

    int base = (warp > 0 ? wsum[warp - 1] : 0) + (v - s);  // exclusive prefix
    int b0 = t * 4;
    if (b0 + 3 < nseg) {
        int4 o = make_int4(base, base + c.x, base + c.x + c.y,
                           base + c.x + c.y + c.z);
        ((int4*)g_offsets)[t] = o;
        ((int4*)g_cursor)[t]  = o;
    } else {
        int o = base;
        if (b0     < nseg) { g_offsets[b0]     = o; g_cursor[b0]     = o; } o += c.x;
        if (b0 + 1 < nseg) { g_offsets[b0 + 1] = o; g_cursor[b0 + 1] = o; } o += c.y;
        if (b0 + 2 < nseg) { g_offsets[b0 + 2] = o; g_cursor[b0 + 2] = o; }
    }
    if (t == 1023) g_offsets[nseg] = wsum[31];
}

// ---------------------------------------------------------------- scatter
__global__ void k_scatter(const void* __restrict__ labels, int n, int nseg) {
    __shared__ int s_lab32;
    if (threadIdx.x == 0) s_lab32 = sniff_lab32(labels, n, nseg);
    __syncthreads();
    int lab32 = s_lab32;
    for (int i = blockIdx.x * blockDim.x + threadIdx.x; i < n;
         i += gridDim.x * blockDim.x) {
        int lab = load_label(labels, i, lab32);
        int pos = atomicAdd(&g_cursor[lab], 1);
        g_order[pos] = i;
    }
}

// ---------------------------------------------------------------- gather-reduce
// One CTA per segment. Thread t owns float4-column t (dim4 <= 128).
// Segment's row indices staged through smem in chunks so index loads are
// off the LDG critical path.
#define CHUNK 128
__global__ __launch_bounds__(128, 8)
void k_reduce(const float4* __restrict__ in, float* __restrict__ out, int dim4) {
    __shared__ int sIdx[CHUNK];
    int s = blockIdx.x;
    int t = threadIdx.x;

    int start = g_offsets[s];
    int end   = g_offsets[s + 1];
    int cnt   = end - start;

    const float4* __restrict__ col = in + t;   // uniform-stride base for this thread

    float4 a0 = make_float4(0.f, 0.f, 0.f, 0.f);
    float4 a1 = a0, a2 = a0, a3 = a0;

    for (int base = start; base < end; base += CHUNK) {
        int m = end - base; if (m > CHUNK) m = CHUNK;
        __syncthreads();
        if (t < m) sIdx[t] = g_order[base + t];
        __syncthreads();
        if (t < dim4) {
            int j = 0;
            for (; j + 4 <= m; j += 4) {
                int i0 = sIdx[j], i1 = sIdx[j + 1], i2 = sIdx[j + 2], i3 = sIdx[j + 3];
                float4 v0 = __ldg(col + i0 * dim4);
                float4 v1 = __ldg(col + i1 * dim4);
                float4 v2 = __ldg(col + i2 * dim4);
                float4 v3 = __ldg(col + i3 * dim4);
                a0.x += v0.x; a0.y += v0.y; a0.z += v0.z; a0.w += v0.w;
                a1.x += v1.x; a1.y += v1.y; a1.z += v1.z; a1.w += v1.w;
                a2.x += v2.x; a2.y += v2.y; a2.z += v2.z; a2.w += v2.w;
                a3.x += v3.x; a3.y += v3.y; a3.z += v3.z; a3.w += v3.w;
            }
            for (; j < m; j++) {
                float4 v0 = __ldg(col + sIdx[j] * dim4);
                a0.x += v0.x; a0.y += v0.y; a0.z += v0.z; a0.w += v0.w;
            }
        }
    }

    if (t < dim4) {
        float4 acc;
        acc.x = (a0.x + a1.x) + (a2.x + a3.x);
        acc.y = (a0.y + a1.y) + (a2.y + a3.y);
        acc.z = (a0.z + a1.z) + (a2.z + a3.z);
        acc.w = (a0.w + a1.w) + (a2.w + a3.w);
        float inv = 1.0f / (float)(cnt > 0 ? cnt : 1);
        acc.x *= inv; acc.y *= inv; acc.z *= inv; acc.w *= inv;
        ((float4*)out)[s * dim4 + t] = acc;
    }
}

// ---------------------------------------------------------------- launch
extern "C" void kernel_launch(void* const* d_in, const int* in_sizes, int n_in,
                              void* d_out, int out_size) {
    const float* node_input = (const float*)d_in[0];
    const void*  labels     = d_in[1];

    int n    = in_sizes[1];
    int dim  = in_sizes[0] / n;          // 480
    int nseg = out_size / dim;           // 4096
    int dim4 = dim / 4;                  // 120

    if (n > N_MAX || nseg > S_MAX || dim4 > 128 || (dim & 3)) return;

    k_hist<<<NB_HIST, 256>>>(labels, n, nseg);
    k_scan<<<1, 1024>>>(nseg);
    k_scatter<<<200, 256>>>(labels, n, nseg);
    k_reduce<<<nseg, 128>>>((const float4*)node_input, (float*)d_out, dim4);
}